// round 1
// baseline (speedup 1.0000x reference)
#include <cuda_runtime.h>
#include <cstdint>
#include <math.h>

#define BATCH 8192
#define TDIM 64
#define FDIM 64
#define CWIN 20
#define WWIN 30
#define EF   64
#define BEGIN 15
#define ROWS 49                 // C + W - 1
#define OUT_ROW (5*EF)          // 320
#define OUT_STRIDE (WWIN*OUT_ROW) // 9600 floats per batch

// ---------------------------------------------------------------------------
// Kernel 1: per-batch window stats (mean, std(ddof=1), max, min)
// One CTA per batch. Stage rows [15,64) x 64 feats in smem, then 1920 items.
// ---------------------------------------------------------------------------
__global__ __launch_bounds__(256) void stats_kernel(const float* __restrict__ x,
                                                    float* __restrict__ out) {
    __shared__ float s[ROWS * FDIM];   // 12544 B
    const int b = blockIdx.x;
    const float* xb = x + (size_t)b * TDIM * FDIM + BEGIN * FDIM;

    // coalesced float4 stage (3136 floats = 784 float4; offset 960 floats is 16B aligned)
    const float4* src4 = (const float4*)xb;
    float4* s4 = (float4*)s;
    for (int i = threadIdx.x; i < ROWS * FDIM / 4; i += 256) s4[i] = src4[i];
    __syncthreads();

    float* outb = out + (size_t)b * OUT_STRIDE;
    for (int item = threadIdx.x; item < WWIN * EF; item += 256) {
        const int w = item >> 6;
        const int e = item & 63;
        const float* p = s + w * FDIM + e;   // lane==e -> conflict-free LDS

        float v0 = p[0];
        float sum = v0, mx = v0, mn = v0;
        #pragma unroll
        for (int c = 1; c < CWIN; c++) {
            float v = p[c * FDIM];
            sum += v;
            mx = fmaxf(mx, v);
            mn = fminf(mn, v);
        }
        const float mean = sum * (1.0f / CWIN);
        float var = 0.0f;
        #pragma unroll
        for (int c = 0; c < CWIN; c++) {
            float d = p[c * FDIM] - mean;
            var += d * d;
        }
        const float sd = sqrtf(var * (1.0f / (CWIN - 1)));

        float* o = outb + w * OUT_ROW + e;   // coalesced 128B per field
        o[0]      = mean;
        o[EF]     = sd;
        o[3 * EF] = mx;
        o[4 * EF] = mn;
    }
}

// ---------------------------------------------------------------------------
// Kernel 2: exact descending rank (stable ties by index) per (w,e) column.
// One CTA (1024 thr) per column. key u = ord(-v): ascending u == descending v.
// 15-bit top histogram -> exclusive scan -> grouped scatter -> exact within-bin
// comparison. rank[b] = #{u'<u} + #{u'==u && b'<b}.
// ---------------------------------------------------------------------------
#define NBINS 32768
#define RT 1024
#define DYN_SMEM (NBINS*4 + BATCH*4 + BATCH*2)   // 180224 B

__global__ __launch_bounds__(RT) void rank_kernel(const float* __restrict__ x,
                                                  float* __restrict__ out) {
    extern __shared__ unsigned char dyn[];
    unsigned int*   hist = (unsigned int*)dyn;                       // 128 KB
    unsigned int*   u    = (unsigned int*)(dyn + NBINS * 4);         // 32 KB
    unsigned short* A    = (unsigned short*)(dyn + NBINS * 4 + BATCH * 4); // 16 KB
    __shared__ unsigned int warpSums[32];

    const int col = blockIdx.x;         // col = w*64 + e (adjacent e -> adjacent CTAs)
    const int w = col >> 6;
    const int e = col & 63;
    const int t = threadIdx.x;
    const int lane = t & 31;
    const int wid  = t >> 5;
    const int row = BEGIN + w + (CWIN - 1);   // 34 + w

    for (int i = t; i < NBINS; i += RT) hist[i] = 0;

    // load column (strided gather; adjacent-e CTAs share 32B sectors in L2)
    unsigned int myu[8];
    #pragma unroll
    for (int k = 0; k < 8; k++) {
        const int b = t + k * RT;
        float v = __ldg(&x[(size_t)b * TDIM * FDIM + row * FDIM + e]);
        unsigned int f = __float_as_uint(-v);
        unsigned int o = (f & 0x80000000u) ? ~f : (f | 0x80000000u);
        myu[k] = o;
        u[b] = o;
    }
    __syncthreads();

    #pragma unroll
    for (int k = 0; k < 8; k++) atomicAdd(&hist[myu[k] >> 17], 1u);
    __syncthreads();

    // exclusive scan of 32768 bins: each warp scans a contiguous 1024-bin chunk
    // (conflict-free: lane-consecutive bins per round), then block-combine.
    const int wbase = wid * 1024;
    unsigned int carry = 0;
    #pragma unroll
    for (int r = 0; r < 32; r++) {
        unsigned int v = hist[wbase + r * 32 + lane];
        unsigned int inc = v;
        #pragma unroll
        for (int d = 1; d < 32; d <<= 1) {
            unsigned int n = __shfl_up_sync(0xffffffffu, inc, d);
            if (lane >= d) inc += n;
        }
        hist[wbase + r * 32 + lane] = (inc - v) + carry;   // exclusive within chunk
        carry += __shfl_sync(0xffffffffu, inc, 31);
    }
    if (lane == 31) warpSums[wid] = carry;
    __syncthreads();
    if (wid == 0) {
        unsigned int orig = warpSums[lane];
        unsigned int inc = orig;
        #pragma unroll
        for (int d = 1; d < 32; d <<= 1) {
            unsigned int n = __shfl_up_sync(0xffffffffu, inc, d);
            if (lane >= d) inc += n;
        }
        warpSums[lane] = inc - orig;   // exclusive chunk offsets
    }
    __syncthreads();
    {
        const unsigned int add = warpSums[wid];
        if (add) {
            #pragma unroll
            for (int r = 0; r < 32; r++) hist[wbase + r * 32 + lane] += add;
        }
    }
    __syncthreads();

    // grouped scatter: hist[bin] walks from excl[bin] to incl[bin]
    #pragma unroll
    for (int k = 0; k < 8; k++) {
        const int b = t + k * RT;
        unsigned int pos = atomicAdd(&hist[myu[k] >> 17], 1u);
        A[pos] = (unsigned short)b;
    }
    __syncthreads();

    // rank = excl[bin] + within-bin count. After scatter: hist[bin]=incl[bin],
    // and excl[bin] = hist[bin-1] (inclusive of previous bin).
    #pragma unroll
    for (int k = 0; k < 8; k++) {
        const int b = t + k * RT;
        const unsigned int key = myu[k];
        const unsigned int hi = key >> 17;
        const unsigned int start = hi ? hist[hi - 1] : 0u;
        const unsigned int end = hist[hi];
        unsigned int cnt = 0;
        for (unsigned int p = start; p < end; p++) {
            const unsigned int b2 = A[p];
            const unsigned int u2 = u[b2];
            cnt += (u2 < key) || (u2 == key && (int)b2 < b);
        }
        const float r = (float)(start + cnt) * (1.0f / BATCH);
        out[(size_t)b * OUT_STRIDE + w * OUT_ROW + 2 * EF + e] = r;
    }
}

// ---------------------------------------------------------------------------
extern "C" void kernel_launch(void* const* d_in, const int* in_sizes, int n_in,
                              void* d_out, int out_size) {
    const float* x = (const float*)d_in[0];
    float* out = (float*)d_out;

    cudaFuncSetAttribute(rank_kernel, cudaFuncAttributeMaxDynamicSharedMemorySize,
                         DYN_SMEM);

    stats_kernel<<<BATCH, 256>>>(x, out);
    rank_kernel<<<WWIN * EF, RT, DYN_SMEM>>>(x, out);
}